// round 6
// baseline (speedup 1.0000x reference)
#include <cuda_runtime.h>
#include <cstdint>

#define Bb   4
#define Nn   2048
#define Hh   8
#define HG   4            // heads per CTA in gat_mma
#define IN_D 128
#define Oo   32
#define LOG2E 1.44269504f

#define BI   64           // rows per CTA (MMA M)
#define KC   16           // j per chunk (MMA K per chunk)
#define NCH  (Nn/KC)      // 128 chunks

// ---------------- scratch (device globals) ----------------------------------
__device__ float g_Wh[(size_t)Bb*Hh*Nn*Oo];   // [b][h][n][o], tf32-rounded
__device__ float g_asrc[(size_t)Bb*Hh*Nn];
__device__ float g_adst[(size_t)Bb*Hh*Nn];
__device__ float g_maxd[Bb*Hh];

__device__ __forceinline__ float ex2f_fast(float x) {
    float r; asm("ex2.approx.ftz.f32 %0, %1;" : "=f"(r) : "f"(x)); return r;
}
__device__ __forceinline__ float tf32_rn(float x) {
    uint32_t r; asm("cvt.rna.tf32.f32 %0, %1;" : "=r"(r) : "f"(x));
    return __uint_as_float(r);
}

// ============================================================================
// Kernel 1: Wh (tf32-rounded, [b][h][n][o]) + alpha_src/alpha_dst
// grid (Nn/32, Hh, Bb) = 2048 CTAs, 256 threads, ONE head per CTA.
// ============================================================================
__global__ __launch_bounds__(256, 4) void wh_kernel(
    const float* __restrict__ x, const float* __restrict__ W,
    const float* __restrict__ a_src, const float* __restrict__ a_dst)
{
    __shared__ __align__(16) float x_sm[32][IN_D];      // 16 KB
    __shared__ __align__(16) float w_sm[IN_D * Oo];     // 16 KB

    const int b   = blockIdx.z;
    const int h   = blockIdx.y;
    const int n0  = blockIdx.x * 32;
    const int tid = threadIdx.x;
    const int lane = tid & 31;       // = o
    const int wq   = tid >> 5;       // warp -> 4 rows

    {   // x tile: 32*128 floats
        const float4* xg = (const float4*)(x + ((size_t)b*Nn + n0)*IN_D);
        float4* xs = (float4*)&x_sm[0][0];
        #pragma unroll
        for (int k = 0; k < 4; ++k) xs[tid + k*256] = xg[tid + k*256];
    }
    {   // W[h]: 128*32 floats
        const float4* wg = (const float4*)(W + (size_t)h*IN_D*Oo);
        float4* ws = (float4*)w_sm;
        #pragma unroll
        for (int k = 0; k < 4; ++k) ws[tid + k*256] = wg[tid + k*256];
    }
    __syncthreads();

    float acc[4] = {0.f, 0.f, 0.f, 0.f};
    #pragma unroll 8
    for (int f4 = 0; f4 < IN_D/4; ++f4) {
        float4 xv[4];
        #pragma unroll
        for (int r = 0; r < 4; ++r)
            xv[r] = ((const float4*)&x_sm[wq*4 + r][0])[f4];
        #pragma unroll
        for (int u = 0; u < 4; ++u) {
            float wv = w_sm[(f4*4 + u)*Oo + lane];
            acc[0] += (u==0?xv[0].x:u==1?xv[0].y:u==2?xv[0].z:xv[0].w) * wv;
            acc[1] += (u==0?xv[1].x:u==1?xv[1].y:u==2?xv[1].z:xv[1].w) * wv;
            acc[2] += (u==0?xv[2].x:u==1?xv[2].y:u==2?xv[2].z:xv[2].w) * wv;
            acc[3] += (u==0?xv[3].x:u==1?xv[3].y:u==2?xv[3].z:xv[3].w) * wv;
        }
    }

    const float asv = a_src[h*Oo + lane];
    const float adv = a_dst[h*Oo + lane];
    #pragma unroll
    for (int r = 0; r < 4; ++r) {
        int n = n0 + wq*4 + r;
        g_Wh[(((size_t)b*Hh + h)*Nn + n)*Oo + lane] = tf32_rn(acc[r]);
        float ps = acc[r] * asv;
        float pd = acc[r] * adv;
        #pragma unroll
        for (int s = 16; s > 0; s >>= 1) {
            ps += __shfl_xor_sync(~0u, ps, s);
            pd += __shfl_xor_sync(~0u, pd, s);
        }
        if (lane == 0) {
            g_asrc[((size_t)b*Hh + h)*Nn + n] = ps;
            g_adst[((size_t)b*Hh + h)*Nn + n] = pd;
        }
    }
}

// ============================================================================
// Kernel 2: per-(b,h) max of alpha_dst
// ============================================================================
__global__ __launch_bounds__(256) void maxd_kernel()
{
    const int bh  = blockIdx.x;
    const int tid = threadIdx.x;
    float m = -1e30f;
    for (int n = tid; n < Nn; n += 256)
        m = fmaxf(m, g_adst[(size_t)bh*Nn + n]);
    __shared__ float red[256];
    red[tid] = m;
    __syncthreads();
    for (int s = 128; s > 0; s >>= 1) {
        if (tid < s) red[tid] = fmaxf(red[tid], red[tid + s]);
        __syncthreads();
    }
    if (tid == 0) g_maxd[bh] = red[0];
}

// ============================================================================
// Kernel 3: fused masked-softmax + AV via mma.sync.m16n8k8.tf32
// grid (Nn/BI=32, Hh/HG=2, Bb=4) = 256 CTAs; 256 threads; 4 heads per CTA.
// Warp w: local head hL = w>>1, row-half mh = w&1 (32 rows each).
// p-gen: thread -> row ith = tid>>2, j-quad j4 = tid&3.
// SMEM (dynamic, 43008 B):
//   p_sm  [4][64][20]     words 0..5119
//   wh_sm [2][4][16][40]  words 5120..10239
//   ej_sm [2][4][16][2]   words 10240..10495
//   z_sm  [4][64]         words 10496..10751
// ============================================================================
__global__ __launch_bounds__(256, 4) void gat_mma(const float* __restrict__ adj,
                                                  float* __restrict__ out)
{
    extern __shared__ float sm[];
    float* p_sm  = sm;
    float* wh_sm = sm + 5120;
    float* ej_sm = sm + 10240;
    float* z_sm  = sm + 10496;

    const int tid  = threadIdx.x;
    const int lane = tid & 31;
    const int wid  = tid >> 5;       // 0..7
    const int hL   = wid >> 1;       // local mma head 0..3
    const int mh   = wid & 1;        // row half
    const int b    = blockIdx.z;
    const int h0   = blockIdx.y * HG;
    const int i0   = blockIdx.x * BI;
    const int ith  = tid >> 2;       // p-gen row 0..63
    const int j4   = tid & 3;        // p-gen j-quad
    const int iglob = i0 + ith;
    const int g  = lane >> 2;
    const int t4 = lane & 3;

    // per-(h,i) hoisted exponentials: w = max(E1i*E1j, E2i*E2j) * mask
    float E1i[HG], E2i[HG], zacc[HG];
    #pragma unroll
    for (int h = 0; h < HG; ++h) {
        float s  = g_asrc[((size_t)(b*Hh + h0 + h))*Nn + iglob];
        float md = g_maxd[b*Hh + h0 + h];
        float t  = s + md;
        float m  = fmaxf(t, 0.2f*t);                 // lrelu monotone -> row max
        E1i[h] = ex2f_fast((s - m)*LOG2E);
        E2i[h] = ex2f_fast((0.2f*s - m)*LOG2E);
        zacc[h] = 0.f;
    }

    const float4* arow  = (const float4*)(adj + ((size_t)b*Nn + iglob)*Nn);
    const float*  whg   = g_Wh + ((size_t)b*Hh + h0)*Nn*Oo;
    const float*  adstb = g_adst + ((size_t)b*Hh + h0)*Nn;

    // ---- prologue: stage wh tile 0 and ej tile 0 into buf 0 ----
    #pragma unroll
    for (int r = 0; r < 2; ++r) {
        int q = tid + r*256;                 // 0..511
        int h = q >> 7, k = (q >> 3) & 15, ng = q & 7;
        float4 v = *(const float4*)(whg + ((size_t)h*Nn + k)*Oo + ng*4);
        *(float4*)(wh_sm + h*640 + k*40 + ng*4) = v;
    }
    if (tid < 64) {
        int h = tid >> 4, j = tid & 15;
        float dl = adstb[(size_t)h*Nn + j] * LOG2E;
        ej_sm[h*32 + j*2 + 0] = ex2f_fast(dl);
        ej_sm[h*32 + j*2 + 1] = ex2f_fast(0.2f*dl);
    }
    float4 adjv = arow[j4];          // chunk-0 adj prefetch

    float acc[2][4][4];
    #pragma unroll
    for (int m = 0; m < 2; ++m)
        #pragma unroll
        for (int nt = 0; nt < 4; ++nt)
            #pragma unroll
            for (int r = 0; r < 4; ++r) acc[m][nt][r] = 0.f;

    __syncthreads();

    for (int c = 0; c < NCH; ++c) {
        const int buf = c & 1;
        const int jb  = c*KC + j4*4;

        // prefetch wh tile (c+1) into regs
        float4 whpf[2];
        if (c + 1 < NCH) {
            #pragma unroll
            for (int r = 0; r < 2; ++r) {
                int q = tid + r*256;
                int h = q >> 7, k = (q >> 3) & 15, ng = q & 7;
                whpf[r] = *(const float4*)(whg + ((size_t)h*Nn + (c+1)*KC + k)*Oo + ng*4);
            }
        }
        // prefetch ej (c+1) into regs
        float e1n = 0.f, e2n = 0.f;
        if (c + 1 < NCH && tid < 64) {
            int h = tid >> 4, j = tid & 15;
            float dl = adstb[(size_t)h*Nn + (c+1)*KC + j] * LOG2E;
            e1n = ex2f_fast(dl);
            e2n = ex2f_fast(0.2f*dl);
        }

        // mask (shared across the 4 heads)
        float msk[4];
        msk[0] = (adjv.x > 0.f || (jb + 0) == iglob) ? 1.f : 0.f;
        msk[1] = (adjv.y > 0.f || (jb + 1) == iglob) ? 1.f : 0.f;
        msk[2] = (adjv.z > 0.f || (jb + 2) == iglob) ? 1.f : 0.f;
        msk[3] = (adjv.w > 0.f || (jb + 3) == iglob) ? 1.f : 0.f;

        // ---- p-gen for 4 heads ----
        #pragma unroll
        for (int h = 0; h < HG; ++h) {
            const float4* ejp = (const float4*)(ej_sm + buf*128 + h*32 + j4*8);
            float4 ea = ejp[0];   // (e1_j0,e2_j0,e1_j1,e2_j1)
            float4 eb = ejp[1];
            float w0 = fmaxf(E1i[h]*ea.x, E2i[h]*ea.y) * msk[0];
            float w1 = fmaxf(E1i[h]*ea.z, E2i[h]*ea.w) * msk[1];
            float w2 = fmaxf(E1i[h]*eb.x, E2i[h]*eb.y) * msk[2];
            float w3 = fmaxf(E1i[h]*eb.z, E2i[h]*eb.w) * msk[3];
            w0 = tf32_rn(w0); w1 = tf32_rn(w1);
            w2 = tf32_rn(w2); w3 = tf32_rn(w3);
            zacc[h] += (w0 + w1) + (w2 + w3);
            *(float4*)(p_sm + h*1280 + ith*20 + j4*4) = make_float4(w0, w1, w2, w3);
        }

        __syncthreads();          // p ready; wh_sm[buf] ready

        if (c + 1 < NCH) adjv = arow[(c+1)*4 + j4];   // adj prefetch

        // ---- mma: warp (hL, mh) ----
        {
            const float* ph = p_sm + hL*1280 + mh*640;
            const float* wt = wh_sm + buf*2560 + hL*640;
            #pragma unroll
            for (int ks = 0; ks < 2; ++ks) {
                const int k0 = ks*8;
                uint32_t bf[4][2];
                #pragma unroll
                for (int nt = 0; nt < 4; ++nt) {
                    bf[nt][0] = __float_as_uint(wt[(k0 + t4)*40 + nt*8 + g]);
                    bf[nt][1] = __float_as_uint(wt[(k0 + t4 + 4)*40 + nt*8 + g]);
                }
                #pragma unroll
                for (int m = 0; m < 2; ++m) {
                    const float* pa = ph + (m*16 + g)*20 + k0;
                    uint32_t a0 = __float_as_uint(pa[t4]);
                    uint32_t a1 = __float_as_uint(pa[160 + t4]);
                    uint32_t a2 = __float_as_uint(pa[t4 + 4]);
                    uint32_t a3 = __float_as_uint(pa[160 + t4 + 4]);
                    #pragma unroll
                    for (int nt = 0; nt < 4; ++nt) {
                        asm volatile(
                          "mma.sync.aligned.m16n8k8.row.col.f32.tf32.tf32.f32 "
                          "{%0,%1,%2,%3}, {%4,%5,%6,%7}, {%8,%9}, {%0,%1,%2,%3};"
                          : "+f"(acc[m][nt][0]), "+f"(acc[m][nt][1]),
                            "+f"(acc[m][nt][2]), "+f"(acc[m][nt][3])
                          : "r"(a0), "r"(a1), "r"(a2), "r"(a3),
                            "r"(bf[nt][0]), "r"(bf[nt][1]));
                    }
                }
            }
        }

        // stage prefetched wh/ej into buf^1
        if (c + 1 < NCH) {
            #pragma unroll
            for (int r = 0; r < 2; ++r) {
                int q = tid + r*256;
                int h = q >> 7, k = (q >> 3) & 15, ng = q & 7;
                *(float4*)(wh_sm + (buf^1)*2560 + h*640 + k*40 + ng*4) = whpf[r];
            }
            if (tid < 64) {
                int h = tid >> 4, j = tid & 15;
                ej_sm[(buf^1)*128 + h*32 + j*2 + 0] = e1n;
                ej_sm[(buf^1)*128 + h*32 + j*2 + 1] = e2n;
            }
        }
        __syncthreads();          // p consumed; next bufs visible
    }

    // ---- Z reduction across the 4 j4-lanes of each row ----
    #pragma unroll
    for (int h = 0; h < HG; ++h) {
        float z = zacc[h];
        z += __shfl_xor_sync(~0u, z, 1);
        z += __shfl_xor_sync(~0u, z, 2);
        if (j4 == 0) z_sm[h*64 + ith] = z;
    }
    __syncthreads();

    // ---- epilogue: normalize, relu, store ----
    {
        float* ob = out + ((size_t)b*Nn + i0 + mh*32)*(Hh*Oo) + (h0 + hL)*Oo;
        #pragma unroll
        for (int m = 0; m < 2; ++m) {
            int r0 = m*16 + g;
            float zi0 = 1.f / z_sm[hL*64 + mh*32 + r0];
            float zi1 = 1.f / z_sm[hL*64 + mh*32 + r0 + 8];
            #pragma unroll
            for (int nt = 0; nt < 4; ++nt) {
                int o = nt*8 + 2*t4;
                float2 v0, v1;
                v0.x = fmaxf(acc[m][nt][0]*zi0, 0.f);
                v0.y = fmaxf(acc[m][nt][1]*zi0, 0.f);
                v1.x = fmaxf(acc[m][nt][2]*zi1, 0.f);
                v1.y = fmaxf(acc[m][nt][3]*zi1, 0.f);
                *(float2*)(ob + (size_t)r0*(Hh*Oo) + o)       = v0;
                *(float2*)(ob + (size_t)(r0 + 8)*(Hh*Oo) + o) = v1;
            }
        }
    }
}

// ============================================================================
extern "C" void kernel_launch(void* const* d_in, const int* in_sizes, int n_in,
                              void* d_out, int out_size)
{
    (void)in_sizes; (void)n_in; (void)out_size;
    const float* x     = (const float*)d_in[0];
    const float* adj   = (const float*)d_in[1];
    const float* W     = (const float*)d_in[2];
    const float* a_src = (const float*)d_in[3];
    const float* a_dst = (const float*)d_in[4];
    float* out = (float*)d_out;

    wh_kernel<<<dim3(Nn/32, Hh, Bb), 256>>>(x, W, a_src, a_dst);
    maxd_kernel<<<Bb*Hh, 256>>>();

    static const int smem_bytes = 43008;
    cudaFuncSetAttribute(gat_mma, cudaFuncAttributeMaxDynamicSharedMemorySize,
                         smem_bytes);
    gat_mma<<<dim3(Nn/BI, Hh/HG, Bb), 256, smem_bytes>>>(adj, out);
}

// round 7
// speedup vs baseline: 1.7809x; 1.7809x over previous
#include <cuda_runtime.h>
#include <cstdint>

#define Bb   4
#define Nn   2048
#define Hh   8
#define HG   4            // heads per CTA in gat_mma
#define IN_D 128
#define Oo   32
#define LOG2E 1.44269504f

#define BI   64           // rows per CTA (MMA M)
#define KC   16           // j per chunk (MMA K per chunk)
#define NCH  (Nn/KC)      // 128 chunks

// ---------------- scratch (device globals) ----------------------------------
__device__ float g_Wh[(size_t)Bb*Hh*Nn*Oo];   // [b][h][n][o], tf32-rounded
__device__ float g_asrc[(size_t)Bb*Hh*Nn];
__device__ float g_adst[(size_t)Bb*Hh*Nn];
__device__ float g_maxd[Bb*Hh];

__device__ __forceinline__ float ex2f_fast(float x) {
    float r; asm("ex2.approx.ftz.f32 %0, %1;" : "=f"(r) : "f"(x)); return r;
}
__device__ __forceinline__ float tf32_rn(float x) {
    uint32_t r; asm("cvt.rna.tf32.f32 %0, %1;" : "=r"(r) : "f"(x));
    return __uint_as_float(r);
}

// ============================================================================
// Kernel 1: Wh (tf32-rounded, [b][h][n][o]) + alpha_src/alpha_dst
// grid (Nn/32, Hh, Bb) = 2048 CTAs, 256 threads, ONE head per CTA.
// ============================================================================
__global__ __launch_bounds__(256, 4) void wh_kernel(
    const float* __restrict__ x, const float* __restrict__ W,
    const float* __restrict__ a_src, const float* __restrict__ a_dst)
{
    __shared__ __align__(16) float x_sm[32][IN_D];      // 16 KB
    __shared__ __align__(16) float w_sm[IN_D * Oo];     // 16 KB

    const int b   = blockIdx.z;
    const int h   = blockIdx.y;
    const int n0  = blockIdx.x * 32;
    const int tid = threadIdx.x;
    const int lane = tid & 31;       // = o
    const int wq   = tid >> 5;       // warp -> 4 rows

    {   // x tile: 32*128 floats
        const float4* xg = (const float4*)(x + ((size_t)b*Nn + n0)*IN_D);
        float4* xs = (float4*)&x_sm[0][0];
        #pragma unroll
        for (int k = 0; k < 4; ++k) xs[tid + k*256] = xg[tid + k*256];
    }
    {   // W[h]: 128*32 floats
        const float4* wg = (const float4*)(W + (size_t)h*IN_D*Oo);
        float4* ws = (float4*)w_sm;
        #pragma unroll
        for (int k = 0; k < 4; ++k) ws[tid + k*256] = wg[tid + k*256];
    }
    __syncthreads();

    float acc[4] = {0.f, 0.f, 0.f, 0.f};
    #pragma unroll 8
    for (int f4 = 0; f4 < IN_D/4; ++f4) {
        float4 xv[4];
        #pragma unroll
        for (int r = 0; r < 4; ++r)
            xv[r] = ((const float4*)&x_sm[wq*4 + r][0])[f4];
        #pragma unroll
        for (int u = 0; u < 4; ++u) {
            float wv = w_sm[(f4*4 + u)*Oo + lane];
            acc[0] += (u==0?xv[0].x:u==1?xv[0].y:u==2?xv[0].z:xv[0].w) * wv;
            acc[1] += (u==0?xv[1].x:u==1?xv[1].y:u==2?xv[1].z:xv[1].w) * wv;
            acc[2] += (u==0?xv[2].x:u==1?xv[2].y:u==2?xv[2].z:xv[2].w) * wv;
            acc[3] += (u==0?xv[3].x:u==1?xv[3].y:u==2?xv[3].z:xv[3].w) * wv;
        }
    }

    const float asv = a_src[h*Oo + lane];
    const float adv = a_dst[h*Oo + lane];
    #pragma unroll
    for (int r = 0; r < 4; ++r) {
        int n = n0 + wq*4 + r;
        g_Wh[(((size_t)b*Hh + h)*Nn + n)*Oo + lane] = tf32_rn(acc[r]);
        float ps = acc[r] * asv;
        float pd = acc[r] * adv;
        #pragma unroll
        for (int s = 16; s > 0; s >>= 1) {
            ps += __shfl_xor_sync(~0u, ps, s);
            pd += __shfl_xor_sync(~0u, pd, s);
        }
        if (lane == 0) {
            g_asrc[((size_t)b*Hh + h)*Nn + n] = ps;
            g_adst[((size_t)b*Hh + h)*Nn + n] = pd;
        }
    }
}

// ============================================================================
// Kernel 2: per-(b,h) max of alpha_dst
// ============================================================================
__global__ __launch_bounds__(256) void maxd_kernel()
{
    const int bh  = blockIdx.x;
    const int tid = threadIdx.x;
    float m = -1e30f;
    for (int n = tid; n < Nn; n += 256)
        m = fmaxf(m, g_adst[(size_t)bh*Nn + n]);
    __shared__ float red[256];
    red[tid] = m;
    __syncthreads();
    for (int s = 128; s > 0; s >>= 1) {
        if (tid < s) red[tid] = fmaxf(red[tid], red[tid + s]);
        __syncthreads();
    }
    if (tid == 0) g_maxd[bh] = red[0];
}

// ============================================================================
// Kernel 3: fused masked-softmax + AV via mma.sync.m16n8k8.tf32
// grid (Nn/BI=32, Hh/HG=2, Bb=4) = 256 CTAs; 256 threads; 4 heads per CTA.
// __launch_bounds__(256, 2): <=128 regs (NO spills), 2 CTAs/SM (43KB smem x2).
// Warp w: local head hL = w>>1, row-half mh = w&1 (32 rows each).
// p-gen: thread -> row ith = tid>>2, j-quad j4 = tid&3.
// SMEM (dynamic, 43008 B):
//   p_sm  [4][64][20]     words 0..5119
//   wh_sm [2][4][16][40]  words 5120..10239
//   ej_sm [2][4][16][2]   words 10240..10495
//   z_sm  [4][64]         words 10496..10751
// ============================================================================
__global__ __launch_bounds__(256, 2) void gat_mma(const float* __restrict__ adj,
                                                  float* __restrict__ out)
{
    extern __shared__ float sm[];
    float* p_sm  = sm;
    float* wh_sm = sm + 5120;
    float* ej_sm = sm + 10240;
    float* z_sm  = sm + 10496;

    const int tid  = threadIdx.x;
    const int lane = tid & 31;
    const int wid  = tid >> 5;       // 0..7
    const int hL   = wid >> 1;       // local mma head 0..3
    const int mh   = wid & 1;        // row half
    const int b    = blockIdx.z;
    const int h0   = blockIdx.y * HG;
    const int i0   = blockIdx.x * BI;
    const int ith  = tid >> 2;       // p-gen row 0..63
    const int j4   = tid & 3;        // p-gen j-quad
    const int iglob = i0 + ith;
    const int g  = lane >> 2;
    const int t4 = lane & 3;

    // per-(h,i) hoisted exponentials: w = max(E1i*E1j, E2i*E2j) * mask
    float E1i[HG], E2i[HG], zacc[HG];
    #pragma unroll
    for (int h = 0; h < HG; ++h) {
        float s  = g_asrc[((size_t)(b*Hh + h0 + h))*Nn + iglob];
        float md = g_maxd[b*Hh + h0 + h];
        float t  = s + md;
        float m  = fmaxf(t, 0.2f*t);                 // lrelu monotone -> row max
        E1i[h] = ex2f_fast((s - m)*LOG2E);
        E2i[h] = ex2f_fast((0.2f*s - m)*LOG2E);
        zacc[h] = 0.f;
    }

    const float4* arow  = (const float4*)(adj + ((size_t)b*Nn + iglob)*Nn);
    const float*  whg   = g_Wh + ((size_t)b*Hh + h0)*Nn*Oo;
    const float*  adstb = g_adst + ((size_t)b*Hh + h0)*Nn;

    // ---- prologue: stage wh tile 0 and ej tile 0 into buf 0 ----
    #pragma unroll
    for (int r = 0; r < 2; ++r) {
        int q = tid + r*256;                 // 0..511
        int h = q >> 7, k = (q >> 3) & 15, ng = q & 7;
        float4 v = *(const float4*)(whg + ((size_t)h*Nn + k)*Oo + ng*4);
        *(float4*)(wh_sm + h*640 + k*40 + ng*4) = v;
    }
    if (tid < 64) {
        int h = tid >> 4, j = tid & 15;
        float dl = adstb[(size_t)h*Nn + j] * LOG2E;
        ej_sm[h*32 + j*2 + 0] = ex2f_fast(dl);
        ej_sm[h*32 + j*2 + 1] = ex2f_fast(0.2f*dl);
    }
    float4 adjv = arow[j4];          // chunk-0 adj prefetch

    float acc[2][4][4];
    #pragma unroll
    for (int m = 0; m < 2; ++m)
        #pragma unroll
        for (int nt = 0; nt < 4; ++nt)
            #pragma unroll
            for (int r = 0; r < 4; ++r) acc[m][nt][r] = 0.f;

    __syncthreads();

    for (int c = 0; c < NCH; ++c) {
        const int buf = c & 1;
        const int jb  = c*KC + j4*4;

        // prefetch wh tile (c+1) into regs
        float4 whpf[2];
        if (c + 1 < NCH) {
            #pragma unroll
            for (int r = 0; r < 2; ++r) {
                int q = tid + r*256;
                int h = q >> 7, k = (q >> 3) & 15, ng = q & 7;
                whpf[r] = *(const float4*)(whg + ((size_t)h*Nn + (c+1)*KC + k)*Oo + ng*4);
            }
        }
        // prefetch ej (c+1) into regs
        float e1n = 0.f, e2n = 0.f;
        if (c + 1 < NCH && tid < 64) {
            int h = tid >> 4, j = tid & 15;
            float dl = adstb[(size_t)h*Nn + (c+1)*KC + j] * LOG2E;
            e1n = ex2f_fast(dl);
            e2n = ex2f_fast(0.2f*dl);
        }

        // mask (shared across the 4 heads)
        float msk[4];
        msk[0] = (adjv.x > 0.f || (jb + 0) == iglob) ? 1.f : 0.f;
        msk[1] = (adjv.y > 0.f || (jb + 1) == iglob) ? 1.f : 0.f;
        msk[2] = (adjv.z > 0.f || (jb + 2) == iglob) ? 1.f : 0.f;
        msk[3] = (adjv.w > 0.f || (jb + 3) == iglob) ? 1.f : 0.f;

        // ---- p-gen for 4 heads ----
        #pragma unroll
        for (int h = 0; h < HG; ++h) {
            const float4* ejp = (const float4*)(ej_sm + buf*128 + h*32 + j4*8);
            float4 ea = ejp[0];   // (e1_j0,e2_j0,e1_j1,e2_j1)
            float4 eb = ejp[1];
            float w0 = fmaxf(E1i[h]*ea.x, E2i[h]*ea.y) * msk[0];
            float w1 = fmaxf(E1i[h]*ea.z, E2i[h]*ea.w) * msk[1];
            float w2 = fmaxf(E1i[h]*eb.x, E2i[h]*eb.y) * msk[2];
            float w3 = fmaxf(E1i[h]*eb.z, E2i[h]*eb.w) * msk[3];
            w0 = tf32_rn(w0); w1 = tf32_rn(w1);
            w2 = tf32_rn(w2); w3 = tf32_rn(w3);
            zacc[h] += (w0 + w1) + (w2 + w3);
            *(float4*)(p_sm + h*1280 + ith*20 + j4*4) = make_float4(w0, w1, w2, w3);
        }

        __syncthreads();          // p ready; wh_sm[buf] ready

        if (c + 1 < NCH) adjv = arow[(c+1)*4 + j4];   // adj prefetch

        // ---- mma: warp (hL, mh) ----
        {
            const float* ph = p_sm + hL*1280 + mh*640;
            const float* wt = wh_sm + buf*2560 + hL*640;
            #pragma unroll
            for (int ks = 0; ks < 2; ++ks) {
                const int k0 = ks*8;
                uint32_t bf[4][2];
                #pragma unroll
                for (int nt = 0; nt < 4; ++nt) {
                    bf[nt][0] = __float_as_uint(wt[(k0 + t4)*40 + nt*8 + g]);
                    bf[nt][1] = __float_as_uint(wt[(k0 + t4 + 4)*40 + nt*8 + g]);
                }
                #pragma unroll
                for (int m = 0; m < 2; ++m) {
                    const float* pa = ph + (m*16 + g)*20 + k0;
                    uint32_t a0 = __float_as_uint(pa[t4]);
                    uint32_t a1 = __float_as_uint(pa[160 + t4]);
                    uint32_t a2 = __float_as_uint(pa[t4 + 4]);
                    uint32_t a3 = __float_as_uint(pa[160 + t4 + 4]);
                    #pragma unroll
                    for (int nt = 0; nt < 4; ++nt) {
                        asm volatile(
                          "mma.sync.aligned.m16n8k8.row.col.f32.tf32.tf32.f32 "
                          "{%0,%1,%2,%3}, {%4,%5,%6,%7}, {%8,%9}, {%0,%1,%2,%3};"
                          : "+f"(acc[m][nt][0]), "+f"(acc[m][nt][1]),
                            "+f"(acc[m][nt][2]), "+f"(acc[m][nt][3])
                          : "r"(a0), "r"(a1), "r"(a2), "r"(a3),
                            "r"(bf[nt][0]), "r"(bf[nt][1]));
                    }
                }
            }
        }

        // stage prefetched wh/ej into buf^1
        if (c + 1 < NCH) {
            #pragma unroll
            for (int r = 0; r < 2; ++r) {
                int q = tid + r*256;
                int h = q >> 7, k = (q >> 3) & 15, ng = q & 7;
                *(float4*)(wh_sm + (buf^1)*2560 + h*640 + k*40 + ng*4) = whpf[r];
            }
            if (tid < 64) {
                int h = tid >> 4, j = tid & 15;
                ej_sm[(buf^1)*128 + h*32 + j*2 + 0] = e1n;
                ej_sm[(buf^1)*128 + h*32 + j*2 + 1] = e2n;
            }
        }
        __syncthreads();          // p consumed; next bufs visible
    }

    // ---- Z reduction across the 4 j4-lanes of each row ----
    #pragma unroll
    for (int h = 0; h < HG; ++h) {
        float z = zacc[h];
        z += __shfl_xor_sync(~0u, z, 1);
        z += __shfl_xor_sync(~0u, z, 2);
        if (j4 == 0) z_sm[h*64 + ith] = z;
    }
    __syncthreads();

    // ---- epilogue: normalize, relu, store ----
    {
        float* ob = out + ((size_t)b*Nn + i0 + mh*32)*(Hh*Oo) + (h0 + hL)*Oo;
        #pragma unroll
        for (int m = 0; m < 2; ++m) {
            int r0 = m*16 + g;
            float zi0 = 1.f / z_sm[hL*64 + mh*32 + r0];
            float zi1 = 1.f / z_sm[hL*64 + mh*32 + r0 + 8];
            #pragma unroll
            for (int nt = 0; nt < 4; ++nt) {
                int o = nt*8 + 2*t4;
                float2 v0, v1;
                v0.x = fmaxf(acc[m][nt][0]*zi0, 0.f);
                v0.y = fmaxf(acc[m][nt][1]*zi0, 0.f);
                v1.x = fmaxf(acc[m][nt][2]*zi1, 0.f);
                v1.y = fmaxf(acc[m][nt][3]*zi1, 0.f);
                *(float2*)(ob + (size_t)r0*(Hh*Oo) + o)       = v0;
                *(float2*)(ob + (size_t)(r0 + 8)*(Hh*Oo) + o) = v1;
            }
        }
    }
}

// ============================================================================
extern "C" void kernel_launch(void* const* d_in, const int* in_sizes, int n_in,
                              void* d_out, int out_size)
{
    (void)in_sizes; (void)n_in; (void)out_size;
    const float* x     = (const float*)d_in[0];
    const float* adj   = (const float*)d_in[1];
    const float* W     = (const float*)d_in[2];
    const float* a_src = (const float*)d_in[3];
    const float* a_dst = (const float*)d_in[4];
    float* out = (float*)d_out;

    wh_kernel<<<dim3(Nn/32, Hh, Bb), 256>>>(x, W, a_src, a_dst);
    maxd_kernel<<<Bb*Hh, 256>>>();

    static const int smem_bytes = 43008;
    cudaFuncSetAttribute(gat_mma, cudaFuncAttributeMaxDynamicSharedMemorySize,
                         smem_bytes);
    gat_mma<<<dim3(Nn/BI, Hh/HG, Bb), 256, smem_bytes>>>(adj, out);
}